// round 11
// baseline (speedup 1.0000x reference)
#include <cuda_runtime.h>
#include <cuda_fp16.h>

// Bilinear flow warp. input1: [B,C,H,W] fp32, flow: [B,2,H,W] fp32.
// Fixed shapes: B=8, C=64, H=256, W=448.
//
// Pass A: NCHW fp32 -> NHWC fp16 scratch. fp16 conversion happens BEFORE the
//         smem transpose tile (half2 chunk-major, stride 66), cutting per-thread
//         LSU ops 44 -> 24.
// Pass B: 4-corner gather (corner = 64 contiguous fp16 ch = 128B), MLP=8
//         batched LDGs, uint4 weight/offset loads, half2 FMA blend, chunk-major
//         fp16 result tile, wide (LDS.64 + 2x STG.64) NCHW fp32 writeback.

#define B_   8
#define C_   64
#define H_   256
#define W_   448
#define HW_  (H_ * W_)            // 114688
#define CHW_ (C_ * HW_)           // 7340032
#define TILES_PER_B (HW_ / 64)    // 1792 (W=448 divisible by 64: tile stays in one row)

// ~117 MB scratch: input in NHWC fp16 layout [B, H, W, C]
__device__ static __half g_nhwc[(size_t)B_ * HW_ * C_];

static __device__ __forceinline__ unsigned int h2bits(__half2 h) {
    return *(unsigned int*)&h;
}
static __device__ __forceinline__ __half2 bits2h(unsigned int u) {
    return *(__half2*)&u;
}

// ---------------------------------------------------------------------------
// Kernel A: NCHW fp32 -> NHWC fp16.  Tile = 64 ch x 64 px, 256 threads.
// smem tile is half2 chunk-major: s16[cw][px], stride 66 (2-way conflicts max).
// ---------------------------------------------------------------------------
__global__ void __launch_bounds__(256) nchw_to_nhwc_f16(const float* __restrict__ in)
{
    __shared__ __half2 s16[32 * 66];   // [cw][px], cw = channel pair, stride 66

    int blk  = blockIdx.x;
    int b    = blk / TILES_PER_B;
    int tile = blk - b * TILES_PER_B;
    int px0  = tile * 64;
    int tid  = threadIdx.x;

    // ---- load + convert: thread handles (cw, 4 px). 2 LDG.128 + 2 STS.64. ----
    #pragma unroll
    for (int it = 0; it < 2; ++it) {
        int idx = it * 256 + tid;
        int cw  = idx >> 4;              // 0..31 (channels 2cw, 2cw+1)
        int px4 = (idx & 15) * 4;        // 0..60
        const float* src = in + b * CHW_ + (2 * cw) * HW_ + px0 + px4;
        float4 va = *(const float4*)src;          // channel 2cw,   4 px
        float4 vb = *(const float4*)(src + HW_);  // channel 2cw+1, 4 px
        __half2* sp = &s16[cw * 66 + px4];
        *(uint2*)(sp)     = make_uint2(h2bits(__floats2half2_rn(va.x, vb.x)),
                                       h2bits(__floats2half2_rn(va.y, vb.y)));
        *(uint2*)(sp + 2) = make_uint2(h2bits(__floats2half2_rn(va.z, vb.z)),
                                       h2bits(__floats2half2_rn(va.w, vb.w)));
    }
    __syncthreads();

    // ---- writeback: lane = cw, each warp covers 8 px rows of 128B. ----
    {
        int wid  = tid >> 5;
        int lane = tid & 31;
        unsigned int* dst = (unsigned int*)(g_nhwc + (size_t)(b * HW_ + px0) * 64);
        #pragma unroll
        for (int k = 0; k < 8; ++k) {
            int px = wid * 8 + k;
            dst[px * 32 + lane] = h2bits(s16[lane * 66 + px]);   // 2-way LDS, coalesced STG
        }
    }
}

// ---------------------------------------------------------------------------
// Kernel B: gather from NHWC fp16, write NCHW fp32.
// Block = 256 threads handles 64 consecutive pixels (one row) x 64 channels.
// ---------------------------------------------------------------------------
__global__ void __launch_bounds__(256, 8) warp_gather_f16(
    const float* __restrict__ flow,   // [B,2,H,W]
    float* __restrict__ out)          // [B,C,H,W]
{
    __shared__ alignas(16) __half2 s_wh[64][4];  // per-pixel corner weights (half2-bcast)
    __shared__ alignas(16) int     s_o[64][4];   // per-pixel corner base offsets (half idx)
    __shared__ __half2 s_r2[32 * 66];            // result tile [cw][px], stride 66

    int blk  = blockIdx.x;
    int b    = blk / TILES_PER_B;
    int tile = blk - b * TILES_PER_B;
    int rem0 = tile * 64;
    int tid  = threadIdx.x;

    // ---- phase 1: one thread per (pixel, corner) ----
    {
        int px     = tid & 63;
        int corner = tid >> 6;           // 0:(y0,x0) 1:(y0,x1) 2:(y1,x0) 3:(y1,x1)
        int rem = rem0 + px;
        int h   = rem / W_;
        int w   = rem - h * W_;

        const float* fl = flow + b * 2 * HW_ + rem;
        float fx = __ldg(fl);
        float fy = __ldg(fl + HW_);

        float x = (float)w + fx;
        float y = (float)h + fy;

        float x0f = floorf(x);
        float y0f = floorf(y);

        int cx = corner & 1;
        int cy = corner >> 1;

        float wx1 = x - x0f;
        float wy1 = y - y0f;
        float wx = cx ? wx1 : (1.0f - wx1);
        float wy = cy ? wy1 : (1.0f - wy1);

        int xi = (int)x0f + cx;
        int yi = (int)y0f + cy;
        float valid = (xi >= 0 && xi < W_ && yi >= 0 && yi < H_) ? 1.0f : 0.0f;
        xi = min(max(xi, 0), W_ - 1);
        yi = min(max(yi, 0), H_ - 1);

        s_wh[px][corner] = __float2half2_rn(wx * wy * valid);
        s_o[px][corner]  = ((b * H_ + yi) * W_ + xi) * 64;
    }
    __syncthreads();

    // ---- phase 2: 8 warps x 8 pixels; lane covers channels (2*lane, 2*lane+1).
    //      MLP=8 (2 px x 4 corners), uint4 offset/weight loads, half2 blend,
    //      chunk-major STS (2-way max). ----
    {
        int wid  = tid >> 5;
        int lane = tid & 31;

        #pragma unroll
        for (int hblk = 0; hblk < 4; ++hblk) {
            int pbase = wid * 8 + hblk * 2;

            __half2 v[2][4];
            #pragma unroll
            for (int j = 0; j < 2; ++j) {
                uint4 ov = *(const uint4*)(&s_o[pbase + j][0]);   // 1 LDS.128
                v[j][0] = __ldg((const __half2*)(g_nhwc + (int)ov.x) + lane);
                v[j][1] = __ldg((const __half2*)(g_nhwc + (int)ov.y) + lane);
                v[j][2] = __ldg((const __half2*)(g_nhwc + (int)ov.z) + lane);
                v[j][3] = __ldg((const __half2*)(g_nhwc + (int)ov.w) + lane);
            }

            #pragma unroll
            for (int j = 0; j < 2; ++j) {
                int p = pbase + j;
                uint4 wv = *(const uint4*)(&s_wh[p][0]);          // 1 LDS.128
                __half2 r = __hfma2(v[j][0], bits2h(wv.x),
                            __hfma2(v[j][1], bits2h(wv.y),
                            __hfma2(v[j][2], bits2h(wv.z),
                            __hmul2(v[j][3], bits2h(wv.w)))));
                s_r2[lane * 66 + p] = r;
            }
        }
    }
    __syncthreads();

    // ---- phase 3: wide NCHW fp32 writeback.
    //      Warp handles 4 cw rows; lane = pixel pair: LDS.64 + 2x STG.64. ----
    {
        int wid  = tid >> 5;
        int lane = tid & 31;
        float* dst = out + b * CHW_ + rem0;
        #pragma unroll
        for (int i = 0; i < 4; ++i) {
            int cw = wid * 4 + i;
            uint2 hh = *(const uint2*)&s_r2[cw * 66 + 2 * lane];  // px 2l, 2l+1
            float2 f0 = __half22float2(bits2h(hh.x));   // (ch 2cw, 2cw+1) @ px 2l
            float2 f1 = __half22float2(bits2h(hh.y));   // (ch 2cw, 2cw+1) @ px 2l+1
            *(float2*)(dst + (2 * cw)     * HW_ + 2 * lane) = make_float2(f0.x, f1.x);
            *(float2*)(dst + (2 * cw + 1) * HW_ + 2 * lane) = make_float2(f0.y, f1.y);
        }
    }
}

extern "C" void kernel_launch(void* const* d_in, const int* in_sizes, int n_in,
                              void* d_out, int out_size)
{
    const float* img  = (const float*)d_in[0];
    const float* flow = (const float*)d_in[1];
    float* out = (float*)d_out;

    const int blocks = B_ * TILES_PER_B;   // 14336
    nchw_to_nhwc_f16<<<blocks, 256>>>(img);
    warp_gather_f16<<<blocks, 256>>>(flow, out);
}